// round 9
// baseline (speedup 1.0000x reference)
#include <cuda_runtime.h>
#include <cuda_bf16.h>
#include <stdint.h>
#include <math.h>

#define NB   64
#define NQ   900
#define NT   128
#define NCLS 91
#define NSEG 8
#define SEGW 113    // 8*113 = 904 >= 900
#define LK   16
#define CTS  928    // transposed column stride

typedef unsigned long long u64;
typedef unsigned int       u32;

// Transposed cost copy: g_Ct[b][col][q] (column-contiguous, for exhaustion rescans)
__device__ float g_Ct[(size_t)NB * NT * CTS];

__device__ __forceinline__ u32 f2ord(float f) {
    u32 u = __float_as_uint(f);
    return (u & 0x80000000u) ? ~u : (u | 0x80000000u);
}
__device__ __forceinline__ u64 umin64(u64 a, u64 b) { return a < b ? a : b; }
__device__ __forceinline__ u64 umax64(u64 a, u64 b) { return a < b ? b : a; }
__device__ __forceinline__ u32 redux_min(u32 v) {
    u32 r;
    asm("redux.sync.min.u32 %0, %1, 0xffffffff;" : "=r"(r) : "r"(v));
    return r;
}
// exact warp-wide u64 min (keys unique)
__device__ __forceinline__ u64 wredmin(u64 k) {
    u32 hi = (u32)(k >> 32);
    u32 mh = redux_min(hi);
    u32 lo = (hi == mh) ? (u32)k : 0xFFFFFFFFu;
    u32 ml = redux_min(lo);
    return ((u64)mh << 32) | ml;
}

// ---------------------------------------------------------------------------
// Kernel 1: cost matrix (row-major) + transposed copy to g_Ct.
// ---------------------------------------------------------------------------
__global__ void __launch_bounds__(256) cost_kernel(
    const float* __restrict__ logits,
    const float* __restrict__ pboxes,
    const int*   __restrict__ labels,
    const float* __restrict__ tboxes,
    float* __restrict__ Cout)
{
    const int b    = blockIdx.y;
    const int tid  = threadIdx.x;
    const int lane = tid & 31;
    const int wid  = tid >> 5;
    const int q0   = blockIdx.x * 16;

    __shared__ float4 s_tb[NT];
    __shared__ float4 s_tx[NT];
    __shared__ float  s_ta[NT];
    __shared__ int    s_lab[NT];
    __shared__ float  s_exp[8][92];
    __shared__ float  s_t[16][132];

    if (tid < NT) {
        const float* tb = tboxes + ((size_t)b * NT + tid) * 4;
        float cx = tb[0], cy = tb[1], w = tb[2], h = tb[3];
        s_tb[tid] = make_float4(cx, cy, w, h);
        float x0 = cx - 0.5f * w, y0 = cy - 0.5f * h;
        float x1 = cx + 0.5f * w, y1 = cy + 0.5f * h;
        s_tx[tid] = make_float4(x0, y0, x1, y1);
        s_ta[tid] = (x1 - x0) * (y1 - y0);
        s_lab[tid] = labels[b * NT + tid];
    }
    __syncthreads();

    #pragma unroll
    for (int rr = 0; rr < 2; rr++) {
        const int qi = rr * 8 + wid;
        const int q  = q0 + qi;
        if (q >= NQ) continue;

        const float* lr = logits + ((size_t)b * NQ + q) * NCLS;
        float l0 = lr[lane];
        float l1 = lr[lane + 32];
        float l2 = (lane + 64 < NCLS) ? lr[lane + 64] : -INFINITY;
        float m = fmaxf(fmaxf(l0, l1), l2);
        #pragma unroll
        for (int o = 16; o; o >>= 1) m = fmaxf(m, __shfl_xor_sync(0xffffffffu, m, o));
        float e0 = expf(l0 - m), e1 = expf(l1 - m);
        float e2 = (lane + 64 < NCLS) ? expf(l2 - m) : 0.0f;
        float ssum = e0 + e1 + e2;
        #pragma unroll
        for (int o = 16; o; o >>= 1) ssum += __shfl_xor_sync(0xffffffffu, ssum, o);
        s_exp[wid][lane] = e0;
        s_exp[wid][lane + 32] = e1;
        if (lane + 64 < NCLS) s_exp[wid][lane + 64] = e2;
        __syncwarp();
        float inv = 1.0f / ssum;

        const float* pbp = pboxes + ((size_t)b * NQ + q) * 4;
        float pcx = pbp[0], pcy = pbp[1], pw = pbp[2], ph = pbp[3];
        float px0 = pcx - 0.5f * pw, py0 = pcy - 0.5f * ph;
        float px1 = pcx + 0.5f * pw, py1 = pcy + 0.5f * ph;
        float pa  = (px1 - px0) * (py1 - py0);

        float cst[4];
        #pragma unroll
        for (int r = 0; r < 4; r++) {
            int t = (lane << 2) | r;
            float4 tb = s_tb[t];
            float4 tx = s_tx[t];
            float pl  = s_exp[wid][s_lab[t]] * inv;
            float l1c = fabsf(pcx - tb.x) + fabsf(pcy - tb.y)
                      + fabsf(pw - tb.z) + fabsf(ph - tb.w);
            float ix0 = fmaxf(px0, tx.x), iy0 = fmaxf(py0, tx.y);
            float ix1 = fminf(px1, tx.z), iy1 = fminf(py1, tx.w);
            float inter = fmaxf(ix1 - ix0, 0.0f) * fmaxf(iy1 - iy0, 0.0f);
            float uni   = pa + s_ta[t] - inter;
            float iou   = inter / uni;
            float cx0 = fminf(px0, tx.x), cy0 = fminf(py0, tx.y);
            float cx1 = fmaxf(px1, tx.z), cy1 = fmaxf(py1, tx.w);
            float ac  = fmaxf(cx1 - cx0, 0.0f) * fmaxf(cy1 - cy0, 0.0f);
            float giou = iou - (ac - uni) / ac;
            cst[r] = -pl + 5.0f * l1c - 2.0f * giou;
        }

        float* crow = Cout + ((size_t)b * NQ + q) * NT;
        *(float4*)(crow + (lane << 2)) = make_float4(cst[0], cst[1], cst[2], cst[3]);
        *(float4*)(&s_t[qi][lane << 2]) = make_float4(cst[0], cst[1], cst[2], cst[3]);
    }
    __syncthreads();

    {
        const int colg = tid >> 1;
        const int half = tid & 1;
        float v[8];
        #pragma unroll
        for (int k = 0; k < 8; k++) v[k] = s_t[half * 8 + k][colg];
        float* dst = g_Ct + ((size_t)b * NT + colg) * CTS + q0 + half * 8;
        *(float4*)(dst)     = make_float4(v[0], v[1], v[2], v[3]);
        *(float4*)(dst + 4) = make_float4(v[4], v[5], v[6], v[7]);
    }
}

// ---------------------------------------------------------------------------
// Kernel 2: greedy.  Dynamic SMEM: sorted top-16 u64 lists per (seg,col)
// (128 KB) + live head cache (8 KB).  Warp 0 runs all steps barrier-free.
// key = (f2ord(v)<<18) | (q<<8) | c  == flattened row-major argmin order.
// ---------------------------------------------------------------------------
extern __shared__ u64 dynsm[];

__global__ void __launch_bounds__(256) greedy_kernel(
    const float* __restrict__ Cmat,
    float* __restrict__ out)
{
    const int b    = blockIdx.x;
    const int tid  = threadIdx.x;
    const int lane = tid & 31;
    const int wid  = tid >> 5;
    const float* __restrict__ Cb = Cmat + (size_t)b * NQ * NT;

    u64* LIST  = dynsm;                    // [(s*NT+c)*LK + e]
    u64* SHEAD = dynsm + NSEG * NT * LK;   // [s*NT + c]

    __shared__ unsigned char sptr[NSEG * NT];
    __shared__ u32 rowdead[32];
    __shared__ int s_src[NT], s_tgt[NT];

    // ---- init: each thread builds 4 (seg,col) sorted top-16 lists ----
    #pragma unroll
    for (int p = 0; p < 4; p++) {
        const int unit = p * 256 + tid;      // 1024 units
        const int s  = unit >> 7;
        const int c  = unit & 127;
        const int qa = s * SEGW;
        const int qb = (qa + SEGW < NQ) ? qa + SEGW : NQ;

        u64 lst[LK];
        #pragma unroll
        for (int e = 0; e < LK; e++) lst[e] = ~0ull;

        int q = qa;
        for (; q + 4 <= qb; q += 4) {
            float v0 = Cb[(q + 0) * NT + c];
            float v1 = Cb[(q + 1) * NT + c];
            float v2 = Cb[(q + 2) * NT + c];
            float v3 = Cb[(q + 3) * NT + c];
            u64 k0 = ((u64)f2ord(v0) << 18) | ((u32)(q + 0) << 8) | (u32)c;
            u64 k1 = ((u64)f2ord(v1) << 18) | ((u32)(q + 1) << 8) | (u32)c;
            u64 k2 = ((u64)f2ord(v2) << 18) | ((u32)(q + 2) << 8) | (u32)c;
            u64 k3 = ((u64)f2ord(v3) << 18) | ((u32)(q + 3) << 8) | (u32)c;
            #pragma unroll
            for (int x = 0; x < 4; x++) {
                u64 k = (x == 0) ? k0 : (x == 1) ? k1 : (x == 2) ? k2 : k3;
                if (k < lst[LK - 1]) {
                    lst[LK - 1] = k;
                    #pragma unroll
                    for (int e = LK - 1; e > 0; e--) {
                        u64 a = lst[e - 1], bb = lst[e];
                        lst[e - 1] = umin64(a, bb);
                        lst[e]     = umax64(a, bb);
                    }
                }
            }
        }
        for (; q < qb; q++) {
            float v = Cb[q * NT + c];
            u64 k = ((u64)f2ord(v) << 18) | ((u32)q << 8) | (u32)c;
            if (k < lst[LK - 1]) {
                lst[LK - 1] = k;
                #pragma unroll
                for (int e = LK - 1; e > 0; e--) {
                    u64 a = lst[e - 1], bb = lst[e];
                    lst[e - 1] = umin64(a, bb);
                    lst[e]     = umax64(a, bb);
                }
            }
        }

        u64* lb = LIST + (size_t)unit * LK;
        #pragma unroll
        for (int e = 0; e < LK; e++) lb[e] = lst[e];
        SHEAD[unit] = lst[0];
        sptr[unit]  = 0;
    }
    if (tid < 32) rowdead[tid] = 0u;
    __syncthreads();

    if (wid != 0) return;

    // ---- warp 0: register column heads ----
    u64 ck[4];
    #pragma unroll
    for (int r = 0; r < 4; r++) {
        const int c = r * 32 + lane;
        u64 m = ~0ull;
        #pragma unroll
        for (int s = 0; s < NSEG; s++) m = umin64(m, SHEAD[s * NT + c]);
        ck[r] = m;
    }

    for (int t = 0; t < NT; t++) {
        u64 h = umin64(umin64(ck[0], ck[1]), umin64(ck[2], ck[3]));
        u64 m = wredmin(h);
        const int i = (int)((m >> 8) & 0x3FFu);
        const int j = (int)(m & 0xFFu);
        if (lane == 0) {
            s_src[t] = i;
            s_tgt[t] = j;
            rowdead[i >> 5] |= (1u << (i & 31));
        }
        __syncwarp();
        if (t == NT - 1) break;

        const int si = i / SEGW;

        u32 exh = 0;
        #pragma unroll
        for (int r = 0; r < 4; r++) {
            if (ck[r] == m)    { ck[r] = ~0ull; continue; }  // matched column
            if (ck[r] == ~0ull) continue;
            const int c    = r * 32 + lane;
            const int hidx = si * NT + c;
            u64 sh = SHEAD[hidx];
            if ((int)((sh >> 8) & 0x3FFu) != i) continue;    // head not dying

            // advance past dead rows within the sorted list
            int p = (int)sptr[hidx] + 1;
            u64 e = ~0ull;
            const u64* lb = LIST + (size_t)hidx * LK;
            while (p < LK) {
                e = lb[p];
                int q = (int)((e >> 8) & 0x3FFu);
                if (!((rowdead[q >> 5] >> (q & 31)) & 1u)) break;
                e = ~0ull;
                p++;
            }
            if (p >= LK) {                 // exhausted -> needs rescan
                exh |= (1u << r);
                SHEAD[hidx] = ~0ull;
                sptr[hidx]  = LK;
            } else {
                SHEAD[hidx] = e;
                sptr[hidx]  = (unsigned char)p;
                if (sh == ck[r]) {
                    u64 nm = ~0ull;
                    #pragma unroll
                    for (int s = 0; s < NSEG; s++) nm = umin64(nm, SHEAD[s * NT + c]);
                    ck[r] = nm;
                }
            }
        }

        // exhaustion: warp-cooperative rescan; rebuild top-8 live entries
        if (__ballot_sync(0xffffffffu, exh != 0)) {
            const int qa = si * SEGW;
            const int qb = (qa + SEGW < NQ) ? qa + SEGW : NQ;
            #pragma unroll
            for (int r = 0; r < 4; r++) {
                u32 mask = __ballot_sync(0xffffffffu, (exh >> r) & 1u);
                while (mask) {
                    const int sl = __ffs(mask) - 1;
                    mask &= mask - 1;
                    const int c2 = r * 32 + sl;
                    const float* col = g_Ct + ((size_t)b * NT + c2) * CTS;

                    u64 cand[4];
                    #pragma unroll
                    for (int k = 0; k < 4; k++) {
                        int q = qa + lane + k * 32;
                        cand[k] = ~0ull;
                        if (q < qb && !((rowdead[q >> 5] >> (q & 31)) & 1u)) {
                            cand[k] = ((u64)f2ord(col[q]) << 18) | ((u32)q << 8) | (u32)c2;
                        }
                    }
                    u64 g[8];
                    #pragma unroll
                    for (int k = 0; k < 8; k++) {
                        u64 lm = umin64(umin64(cand[0], cand[1]), umin64(cand[2], cand[3]));
                        u64 gm = wredmin(lm);
                        g[k] = gm;
                        #pragma unroll
                        for (int x = 0; x < 4; x++) if (cand[x] == gm) cand[x] = ~0ull;
                    }
                    if (lane == sl) {
                        const int hidx2 = si * NT + c2;
                        u64* lb2 = LIST + (size_t)hidx2 * LK;
                        #pragma unroll
                        for (int k = 0; k < 8; k++) lb2[8 + k] = g[k];
                        sptr[hidx2]  = 8;
                        SHEAD[hidx2] = g[0];
                        u64 nm = ~0ull;
                        #pragma unroll
                        for (int s = 0; s < NSEG; s++) nm = umin64(nm, SHEAD[s * NT + c2]);
                        ck[r] = nm;
                    }
                }
            }
        }
        __syncwarp();
    }

    __syncwarp();
    #pragma unroll
    for (int r = 0; r < 4; r++) {
        int t = r * 32 + lane;
        out[b * NT + t]           = (float)s_src[t];
        out[NB * NT + b * NT + t] = (float)s_tgt[t];
    }
}

// ---------------------------------------------------------------------------
extern "C" void kernel_launch(void* const* d_in, const int* in_sizes, int n_in,
                              void* d_out, int out_size) {
    const float* logits = (const float*)d_in[0];
    const float* pboxes = (const float*)d_in[1];
    const int*   labels = (const int*)d_in[2];
    const float* tboxes = (const float*)d_in[3];
    float* out = (float*)d_out;

    float* Cout = out + 2 * NB * NT;

    const int dyn_bytes = (NSEG * NT * LK + NSEG * NT) * (int)sizeof(u64);  // 139264
    cudaFuncSetAttribute(greedy_kernel,
                         cudaFuncAttributeMaxDynamicSharedMemorySize, dyn_bytes);

    dim3 grid1((NQ + 15) / 16, NB);
    cost_kernel<<<grid1, 256>>>(logits, pboxes, labels, tboxes, Cout);
    greedy_kernel<<<NB, 256, dyn_bytes>>>(Cout, out);
}

// round 10
// speedup vs baseline: 1.3028x; 1.3028x over previous
#include <cuda_runtime.h>
#include <cuda_bf16.h>
#include <stdint.h>
#include <math.h>

#define NB   64
#define NQ   900
#define NT   128
#define NCLS 91
#define NSEG 8
#define SEGW 113    // 8*113 = 904 >= 900
#define CTS  928    // transposed column stride

typedef unsigned long long u64;
typedef unsigned int       u32;

// Transposed cost copy: g_Ct[b][col][q] (column-contiguous, for rescans)
__device__ float g_Ct[(size_t)NB * NT * CTS];
// Per-(batch, segment, column) minimum key, built by cost_kernel via atomicMin.
__device__ u64 g_segmin[(size_t)NB * NSEG * NT];

__device__ __forceinline__ u32 f2ord(float f) {
    u32 u = __float_as_uint(f);
    return (u & 0x80000000u) ? ~u : (u | 0x80000000u);
}
__device__ __forceinline__ u64 umin64(u64 a, u64 b) { return a < b ? a : b; }
__device__ __forceinline__ u32 redux_min(u32 v) {
    u32 r;
    asm("redux.sync.min.u32 %0, %1, 0xffffffff;" : "=r"(r) : "r"(v));
    return r;
}
// exact warp-wide u64 min (keys unique)
__device__ __forceinline__ u64 wredmin(u64 k) {
    u32 hi = (u32)(k >> 32);
    u32 mh = redux_min(hi);
    u32 lo = (hi == mh) ? (u32)k : 0xFFFFFFFFu;
    u32 ml = redux_min(lo);
    return ((u64)mh << 32) | ml;
}

// ---------------------------------------------------------------------------
// Kernel 0: reset segment minima (deterministic, graph-replay-safe).
// ---------------------------------------------------------------------------
__global__ void __launch_bounds__(256) init_kernel() {
    const size_t n = (size_t)NB * NSEG * NT;
    const size_t idx = (size_t)blockIdx.x * 256 + threadIdx.x;
    for (size_t p = idx; p < n; p += (size_t)gridDim.x * 256)
        g_segmin[p] = ~0ull;
}

// ---------------------------------------------------------------------------
// Kernel 1: cost matrix (row-major) + transposed copy + segmin atomics.
// ---------------------------------------------------------------------------
__global__ void __launch_bounds__(256) cost_kernel(
    const float* __restrict__ logits,
    const float* __restrict__ pboxes,
    const int*   __restrict__ labels,
    const float* __restrict__ tboxes,
    float* __restrict__ Cout)
{
    const int b    = blockIdx.y;
    const int tid  = threadIdx.x;
    const int lane = tid & 31;
    const int wid  = tid >> 5;
    const int q0   = blockIdx.x * 16;

    __shared__ float4 s_tb[NT];
    __shared__ float4 s_tx[NT];
    __shared__ float  s_ta[NT];
    __shared__ int    s_lab[NT];
    __shared__ float  s_exp[8][92];
    __shared__ float  s_t[16][132];

    if (tid < NT) {
        const float* tb = tboxes + ((size_t)b * NT + tid) * 4;
        float cx = tb[0], cy = tb[1], w = tb[2], h = tb[3];
        s_tb[tid] = make_float4(cx, cy, w, h);
        float x0 = cx - 0.5f * w, y0 = cy - 0.5f * h;
        float x1 = cx + 0.5f * w, y1 = cy + 0.5f * h;
        s_tx[tid] = make_float4(x0, y0, x1, y1);
        s_ta[tid] = (x1 - x0) * (y1 - y0);
        s_lab[tid] = labels[b * NT + tid];
    }
    __syncthreads();

    #pragma unroll
    for (int rr = 0; rr < 2; rr++) {
        const int qi = rr * 8 + wid;
        const int q  = q0 + qi;
        if (q >= NQ) continue;

        const float* lr = logits + ((size_t)b * NQ + q) * NCLS;
        float l0 = lr[lane];
        float l1 = lr[lane + 32];
        float l2 = (lane + 64 < NCLS) ? lr[lane + 64] : -INFINITY;
        float m = fmaxf(fmaxf(l0, l1), l2);
        #pragma unroll
        for (int o = 16; o; o >>= 1) m = fmaxf(m, __shfl_xor_sync(0xffffffffu, m, o));
        float e0 = expf(l0 - m), e1 = expf(l1 - m);
        float e2 = (lane + 64 < NCLS) ? expf(l2 - m) : 0.0f;
        float ssum = e0 + e1 + e2;
        #pragma unroll
        for (int o = 16; o; o >>= 1) ssum += __shfl_xor_sync(0xffffffffu, ssum, o);
        s_exp[wid][lane] = e0;
        s_exp[wid][lane + 32] = e1;
        if (lane + 64 < NCLS) s_exp[wid][lane + 64] = e2;
        __syncwarp();
        float inv = 1.0f / ssum;

        const float* pbp = pboxes + ((size_t)b * NQ + q) * 4;
        float pcx = pbp[0], pcy = pbp[1], pw = pbp[2], ph = pbp[3];
        float px0 = pcx - 0.5f * pw, py0 = pcy - 0.5f * ph;
        float px1 = pcx + 0.5f * pw, py1 = pcy + 0.5f * ph;
        float pa  = (px1 - px0) * (py1 - py0);

        float cst[4];
        #pragma unroll
        for (int r = 0; r < 4; r++) {
            int t = (lane << 2) | r;
            float4 tb = s_tb[t];
            float4 tx = s_tx[t];
            float pl  = s_exp[wid][s_lab[t]] * inv;
            float l1c = fabsf(pcx - tb.x) + fabsf(pcy - tb.y)
                      + fabsf(pw - tb.z) + fabsf(ph - tb.w);
            float ix0 = fmaxf(px0, tx.x), iy0 = fmaxf(py0, tx.y);
            float ix1 = fminf(px1, tx.z), iy1 = fminf(py1, tx.w);
            float inter = fmaxf(ix1 - ix0, 0.0f) * fmaxf(iy1 - iy0, 0.0f);
            float uni   = pa + s_ta[t] - inter;
            float iou   = inter / uni;
            float cx0 = fminf(px0, tx.x), cy0 = fminf(py0, tx.y);
            float cx1 = fmaxf(px1, tx.z), cy1 = fmaxf(py1, tx.w);
            float ac  = fmaxf(cx1 - cx0, 0.0f) * fmaxf(cy1 - cy0, 0.0f);
            float giou = iou - (ac - uni) / ac;
            cst[r] = -pl + 5.0f * l1c - 2.0f * giou;
        }

        float* crow = Cout + ((size_t)b * NQ + q) * NT;
        *(float4*)(crow + (lane << 2)) = make_float4(cst[0], cst[1], cst[2], cst[3]);
        *(float4*)(&s_t[qi][lane << 2]) = make_float4(cst[0], cst[1], cst[2], cst[3]);
    }
    __syncthreads();

    // transpose + segmin atomics: thread -> (col = tid>>1, half = tid&1)
    {
        const int colg = tid >> 1;
        const int half = tid & 1;
        const int a    = q0 + half * 8;
        float v[8];
        #pragma unroll
        for (int k = 0; k < 8; k++) v[k] = s_t[half * 8 + k][colg];

        float* dst = g_Ct + ((size_t)b * NT + colg) * CTS + a;
        *(float4*)(dst)     = make_float4(v[0], v[1], v[2], v[3]);
        *(float4*)(dst + 4) = make_float4(v[4], v[5], v[6], v[7]);

        // rows a..a+7 span at most 2 segments (SEGW=113 > 16)
        const int s0    = a / SEGW;
        const int split = (s0 + 1) * SEGW;
        u64 m0 = ~0ull, m1 = ~0ull;
        #pragma unroll
        for (int k = 0; k < 8; k++) {
            int q = a + k;
            if (q < NQ) {
                u64 key = ((u64)f2ord(v[k]) << 18) | ((u32)q << 8) | (u32)colg;
                if (q < split) m0 = umin64(m0, key);
                else           m1 = umin64(m1, key);
            }
        }
        u64* segb = g_segmin + (size_t)b * NSEG * NT;
        if (m0 != ~0ull) atomicMin(&segb[s0 * NT + colg], m0);
        if (m1 != ~0ull) atomicMin(&segb[(s0 + 1) * NT + colg], m1);
    }
}

// ---------------------------------------------------------------------------
// Kernel 2: greedy matching.  One block per batch; 8 warps.
// Replicated argmin (reads only) / barrier / owner-exclusive repair / barrier.
// key = (f2ord(v)<<18) | (q<<8) | c == flattened row-major argmin order.
// ---------------------------------------------------------------------------
__global__ void __launch_bounds__(256) greedy_kernel(float* __restrict__ out)
{
    const int b    = blockIdx.x;
    const int tid  = threadIdx.x;
    const int lane = tid & 31;
    const int wid  = tid >> 5;

    __shared__ u64 segmin[NSEG][NT];
    __shared__ u64 colkey[NT];
    __shared__ u32 rowdead[32];
    __shared__ int s_src[NT], s_tgt[NT];

    // load segmins (8 KB, coalesced)
    {
        const u64* __restrict__ segb = g_segmin + (size_t)b * NSEG * NT;
        for (int idx = tid; idx < NSEG * NT; idx += 256)
            segmin[idx >> 7][idx & 127] = segb[idx];
    }
    if (tid < 32) rowdead[tid] = 0u;
    __syncthreads();

    if (tid < NT) {
        u64 m = ~0ull;
        #pragma unroll
        for (int s = 0; s < NSEG; s++) m = umin64(m, segmin[s][tid]);
        colkey[tid] = m;
    }
    __syncthreads();

    for (int t = 0; t < NT; t++) {
        // ---- argmin (replicated; reads only) ----
        u64 h = umin64(umin64(colkey[lane], colkey[lane + 32]),
                       umin64(colkey[lane + 64], colkey[lane + 96]));
        u64 m = wredmin(h);
        const int i = (int)((m >> 8) & 0x3FFu);
        const int j = (int)(m & 0xFFu);
        __syncthreads();   // barrier A: all colkey reads complete

        if (tid == 0) {
            s_src[t] = i;
            s_tgt[t] = j;
            colkey[j] = ~0ull;
            rowdead[i >> 5] |= (1u << (i & 31));
        }
        if (t == NT - 1) break;

        const int si = i / SEGW;
        const int qa = si * SEGW;
        const int qb = (qa + SEGW < NQ) ? qa + SEGW : NQ;

        // ---- dirty detection: warp w owns columns 16w..16w+15 ----
        bool dirty = false;
        if (lane < 16) {
            const int c = (wid << 4) + lane;
            if (c != j && colkey[c] != ~0ull) {
                u64 sm = segmin[si][c];
                dirty = (sm != ~0ull) && ((int)((sm >> 8) & 0x3FFu) == i);
            }
        }
        u32 mask = __ballot_sync(0xffffffffu, dirty);

        while (mask) {
            const int sl = __ffs(mask) - 1;
            mask &= mask - 1;
            const int c2 = (wid << 4) + sl;
            const float* col = g_Ct + ((size_t)b * NT + c2) * CTS;

            // rescan segment si (4 pipelined coalesced loads per lane)
            u64 best = ~0ull;
            #pragma unroll
            for (int k = 0; k < 4; k++) {
                const int q = qa + lane + k * 32;
                if (q < qb && q != i && !((rowdead[q >> 5] >> (q & 31)) & 1u)) {
                    u64 key = ((u64)f2ord(col[q]) << 18) | ((u32)q << 8) | (u32)c2;
                    best = umin64(best, key);
                }
            }
            u64 nk = wredmin(best);
            if (lane == sl) {
                segmin[si][c2] = nk;
                u64 nc = ~0ull;
                #pragma unroll
                for (int s = 0; s < NSEG; s++) nc = umin64(nc, segmin[s][c2]);
                colkey[c2] = nc;
            }
        }
        __syncthreads();   // barrier B: repairs visible for next argmin
    }

    __syncthreads();
    if (tid < NT) {
        out[b * NT + tid]           = (float)s_src[tid];
        out[NB * NT + b * NT + tid] = (float)s_tgt[tid];
    }
}

// ---------------------------------------------------------------------------
extern "C" void kernel_launch(void* const* d_in, const int* in_sizes, int n_in,
                              void* d_out, int out_size) {
    const float* logits = (const float*)d_in[0];
    const float* pboxes = (const float*)d_in[1];
    const int*   labels = (const int*)d_in[2];
    const float* tboxes = (const float*)d_in[3];
    float* out = (float*)d_out;

    float* Cout = out + 2 * NB * NT;

    init_kernel<<<64, 256>>>();
    dim3 grid1((NQ + 15) / 16, NB);
    cost_kernel<<<grid1, 256>>>(logits, pboxes, labels, tboxes, Cout);
    greedy_kernel<<<NB, 256>>>(out);
}